// round 15
// baseline (speedup 1.0000x reference)
#include <cuda_runtime.h>
#include <cuda_bf16.h>
#include <math.h>
#include <float.h>
#include <stdint.h>

#define Nn 15000
#define Ee 60000
#define Bb 512
#define Dd 64
#define EHh 128
#define DDf 4096   // D*D
#define NSTEPS 6
#define SPAD 136

// ---------------- device scratch ----------------
static __device__ __nv_bfloat16 g_Hb[(size_t)Ee * EHh];    // edge hidden (edge order)
static __device__ __nv_bfloat16 g_W2b[(size_t)DDf * EHh];  // en_w2 bf16 [4096,128]
static __device__ __nv_bfloat16 g_ewb[(size_t)Ee * DDf];   // edge weights (edge order)
static __device__ float g_h[Nn * Dd];                      // node state fp32 (master)
static __device__ __nv_bfloat16 g_mh[Nn * 128];            // [m | h] per node, bf16
static __device__ __nv_bfloat16 g_WcatT[384 * 128];        // interleaved GRU weights^T
static __device__ float g_invdeg[Nn];
static __device__ int   g_eoff[Nn + 1];                    // CSR offsets by target
static __device__ int   g_perm[Ee];                        // edge ids grouped by target
static __device__ int   g_src[Ee];                         // src node per CSR pos
static __device__ int   g_boff[Bb + 1];                    // batch segment offsets
static __device__ float g_lwihT[128 * 256];                // LSTM w_ih^T (k-major)
static __device__ float g_lwhhT[64 * 256];                 // LSTM w_hh^T (k-major)
static __device__ float g_l1T[128 * 64];                   // lin1_w^T (k-major)

// ---------------- helpers ----------------
__device__ __forceinline__ float tanhfast(float x) {
    float y;
    asm("tanh.approx.f32 %0, %1;" : "=f"(y) : "f"(x));
    return y;
}
__device__ __forceinline__ float sigmfast(float x) {
    return fmaf(0.5f, tanhfast(0.5f * x), 0.5f);
}

__device__ __forceinline__ void ldsm_x4(uint32_t* r, const void* p) {
    uint32_t addr = (uint32_t)__cvta_generic_to_shared(p);
    asm volatile("ldmatrix.sync.aligned.m8n8.x4.shared.b16 {%0,%1,%2,%3}, [%4];"
                 : "=r"(r[0]), "=r"(r[1]), "=r"(r[2]), "=r"(r[3]) : "r"(addr));
}
__device__ __forceinline__ void ldsm_x2(uint32_t* r, const void* p) {
    uint32_t addr = (uint32_t)__cvta_generic_to_shared(p);
    asm volatile("ldmatrix.sync.aligned.m8n8.x2.shared.b16 {%0,%1}, [%2];"
                 : "=r"(r[0]), "=r"(r[1]) : "r"(addr));
}
__device__ __forceinline__ void mma_bf16(float* c, const uint32_t* a, const uint32_t* b) {
    asm volatile(
        "mma.sync.aligned.m16n8k16.row.col.f32.bf16.bf16.f32 "
        "{%0,%1,%2,%3}, {%4,%5,%6,%7}, {%8,%9}, {%0,%1,%2,%3};"
        : "+f"(c[0]), "+f"(c[1]), "+f"(c[2]), "+f"(c[3])
        : "r"(a[0]), "r"(a[1]), "r"(a[2]), "r"(a[3]), "r"(b[0]), "r"(b[1]));
}
__device__ __forceinline__ void cp_async16(void* dst, const void* src, int sz) {
    uint32_t d = (uint32_t)__cvta_generic_to_shared(dst);
    asm volatile("cp.async.cg.shared.global [%0], [%1], 16, %2;"
                 :: "r"(d), "l"(src), "r"(sz));
}
__device__ __forceinline__ void cp_commit() { asm volatile("cp.async.commit_group;"); }
template <int N>
__device__ __forceinline__ void cp_wait() {
    asm volatile("cp.async.wait_group %0;" :: "n"(N));
}

// ---------------- merged prep + csr ----------------------------------------------
#define PA0 (Nn * Dd)
#define PA1 (DDf * EHh)
#define PA2 (Ee * EHh)
#define PA3 (384 * 128)
#define PA4 (Bb + 1)
#define PA5 (128 * 256)
#define PA6 (64 * 256)
#define PA7 (128 * 64)
#define PA_TOT (PA0 + PA1 + PA2 + PA3 + PA4 + PA5 + PA6 + PA7)
#define PREP_BLOCKS 148
__global__ void __launch_bounds__(1024) prep_csr_kernel(
    const float* __restrict__ x,
    const float* __restrict__ lw,
    const float* __restrict__ lb,
    const float* __restrict__ w2,
    const float* __restrict__ ea,
    const float* __restrict__ w1,
    const float* __restrict__ b1,
    const float* __restrict__ wih,
    const float* __restrict__ whh,
    const int* __restrict__ batch,
    const int* __restrict__ edge_index,
    const float* __restrict__ lstm_wih,
    const float* __restrict__ lstm_whh,
    const float* __restrict__ lin1_w) {
    const int t = threadIdx.x;
    if (blockIdx.x == 0) {
        extern __shared__ int sdyn[];
        int* scnt = sdyn;
        int* scur = sdyn + Nn;
        __shared__ int part[1024];
        for (int i = t; i < Nn; i += 1024) { scnt[i] = 0; scur[i] = 0; }
        __syncthreads();
        for (int e = t; e < Ee; e += 1024)
            atomicAdd(&scnt[edge_index[Ee + e]], 1);
        __syncthreads();
        int loc[15];
        int s = 0;
#pragma unroll
        for (int j = 0; j < 15; j++) {
            int idx = t * 15 + j;
            int v = (idx < Nn) ? scnt[idx] : 0;
            loc[j] = s; s += v;
        }
        part[t] = s;
        __syncthreads();
        for (int off = 1; off < 1024; off <<= 1) {
            int v = (t >= off) ? part[t - off] : 0;
            __syncthreads();
            part[t] += v;
            __syncthreads();
        }
        int excl = part[t] - s;
#pragma unroll
        for (int j = 0; j < 15; j++) {
            int idx = t * 15 + j;
            if (idx < Nn) {
                g_eoff[idx] = excl + loc[j];
                g_invdeg[idx] = 1.0f / fmaxf((float)scnt[idx], 1.0f);
            }
        }
        if (t == 0) g_eoff[Nn] = Ee;
        __syncthreads();
        for (int e = t; e < Ee; e += 1024) {
            int tgt = edge_index[Ee + e];
            int pos = atomicAdd(&scur[tgt], 1);
            int base = g_eoff[tgt] + pos;
            g_perm[base] = e;
            g_src[base] = edge_index[e];
        }
        return;
    }
    const int stride = (PREP_BLOCKS - 1) * 1024;
    for (int idx = (blockIdx.x - 1) * 1024 + t; idx < PA_TOT; idx += stride) {
        if (idx < PA0) {
            int n = idx >> 6, o = idx & 63;
            float acc = lb[o];
            const float* xr = x + n * 15;
            const float* wr = lw + o * 15;
#pragma unroll
            for (int j = 0; j < 15; j++) acc = fmaf(xr[j], wr[j], acc);
            float h = fmaxf(acc, 0.0f);
            g_h[idx] = h;
            g_mh[n * 128 + 64 + o] = __float2bfloat16_rn(h);
        } else if (idx < PA0 + PA1) {
            int q = idx - PA0;
            g_W2b[q] = __float2bfloat16_rn(w2[q]);
        } else if (idx < PA0 + PA1 + PA2) {
            int q = idx - PA0 - PA1;
            int e = q >> 7, k = q & 127;
            float acc = b1[k];
            const float* er = ea + e * 5;
            const float* wr = w1 + k * 5;
#pragma unroll
            for (int j = 0; j < 5; j++) acc = fmaf(er[j], wr[j], acc);
            g_Hb[q] = __float2bfloat16_rn(fmaxf(acc, 0.0f));
        } else if (idx < PA0 + PA1 + PA2 + PA3) {
            int q = idx - PA0 - PA1 - PA2;
            int jf = q >> 7, k = q & 127;
            int ch = jf >> 7;
            int j = jf & 127;
            int d = j >> 1;
            float v = 0.0f;
            if ((j & 1) == 0) { if (k < 64)  v = wih[(ch * 64 + d) * 64 + k]; }
            else              { if (k >= 64) v = whh[(ch * 64 + d) * 64 + (k - 64)]; }
            g_WcatT[jf * 128 + k] = __float2bfloat16_rn(v);
        } else if (idx < PA0 + PA1 + PA2 + PA3 + PA4) {
            int b = idx - PA0 - PA1 - PA2 - PA3;
            int lo = 0, hi = Nn;
            while (lo < hi) {
                int mid = (lo + hi) >> 1;
                if (batch[mid] < b) lo = mid + 1; else hi = mid;
            }
            g_boff[b] = lo;
        } else if (idx < PA0 + PA1 + PA2 + PA3 + PA4 + PA5) {
            int q = idx - PA0 - PA1 - PA2 - PA3 - PA4;
            int k = q >> 8, j = q & 255;
            g_lwihT[q] = lstm_wih[j * 128 + k];
        } else if (idx < PA0 + PA1 + PA2 + PA3 + PA4 + PA5 + PA6) {
            int q = idx - PA0 - PA1 - PA2 - PA3 - PA4 - PA5;
            int k = q >> 8, j = q & 255;
            g_lwhhT[q] = lstm_whh[j * 64 + k];
        } else {
            int q = idx - PA0 - PA1 - PA2 - PA3 - PA4 - PA5 - PA6;
            int k = q >> 6, j = q & 63;
            g_l1T[q] = lin1_w[j * 128 + k];
        }
    }
}

// ---------------- ew GEMM v5: persistent bm-block, bn-loop with B double-buffer --
// One block per bm (469 blocks). A tile loaded once; loop 32 bn chunks:
// prefetch B[n+1] | MMA B[n] | stage | store. 2 barriers/iter.
// smem: A[128][136] | B[2][128][136] | stage[128][136]  = 139264 B (1 block/SM)
#define GB_A  0
#define GB_B0 34816
#define GB_ST (34816 * 3)
#define GB_SMEM (34816 * 4)   // 139264
__global__ void __launch_bounds__(256, 1) gemm_ew_mma(const float* __restrict__ b2) {
    extern __shared__ __align__(16) unsigned char sm[];
    __nv_bfloat16* As = (__nv_bfloat16*)(sm + GB_A);
    __nv_bfloat16* Bbuf = (__nv_bfloat16*)(sm + GB_B0);   // [2][128][136]
    __nv_bfloat16* stage = (__nv_bfloat16*)(sm + GB_ST);

    const int bm = blockIdx.x;   // 0..468
    const int tid = threadIdx.x;
    const int warp = tid >> 5, lane = tid & 31;
    const int wm = (warp >> 2) * 64;
    const int wn = (warp & 3) * 32;

    const int lrow = lane & 15;
    const int lcol8 = ((lane >> 4) & 1) * 8;
    const int lbrow = lane & 7;
    const int lbcol8 = ((lane >> 3) & 1) * 8;
    const int r0 = lane >> 2;
    const int c0 = (lane & 3) * 2;

    // prologue: A tile + B chunk 0 (one group)
#pragma unroll
    for (int u = tid; u < 2048; u += 256) {
        int r = u >> 4, c = (u & 15) * 8;
        int grow = bm * 128 + r;
        cp_async16(&As[r * SPAD + c], &g_Hb[(size_t)grow * 128 + c],
                   (grow < Ee) ? 16 : 0);
        cp_async16(&Bbuf[r * SPAD + c], &g_W2b[(size_t)r * 128 + c], 16);
    }
    cp_commit();

#pragma unroll 1
    for (int bn = 0; bn < 32; bn++) {
        // prefetch next B chunk into the other buffer
        if (bn < 31) {
            __nv_bfloat16* Bn = Bbuf + ((bn + 1) & 1) * 128 * SPAD;
#pragma unroll
            for (int u = tid; u < 2048; u += 256) {
                int r = u >> 4, c = (u & 15) * 8;
                cp_async16(&Bn[r * SPAD + c],
                           &g_W2b[(size_t)((bn + 1) * 128 + r) * 128 + c], 16);
            }
            cp_commit();
            cp_wait<1>();
        } else {
            cp_wait<0>();
        }
        __syncthreads();   // B[bn] (and A) visible; prev iter's store-LDS drained

        const __nv_bfloat16* Bc = Bbuf + (bn & 1) * 128 * SPAD;
        float acc[4][4][4];
#pragma unroll
        for (int mi = 0; mi < 4; mi++)
#pragma unroll
            for (int ni = 0; ni < 4; ni++)
#pragma unroll
                for (int r = 0; r < 4; r++) acc[mi][ni][r] = 0.0f;

#pragma unroll
        for (int k0 = 0; k0 < 128; k0 += 16) {
            uint32_t a[4][4], b[4][2];
#pragma unroll
            for (int mi = 0; mi < 4; mi++)
                ldsm_x4(a[mi], &As[(wm + mi * 16 + lrow) * SPAD + k0 + lcol8]);
#pragma unroll
            for (int ni = 0; ni < 4; ni++)
                ldsm_x2(b[ni], &Bc[(wn + ni * 8 + lbrow) * SPAD + k0 + lbcol8]);
#pragma unroll
            for (int mi = 0; mi < 4; mi++)
#pragma unroll
                for (int ni = 0; ni < 4; ni++)
                    mma_bf16(acc[mi][ni], a[mi], b[ni]);
        }

        // epilogue: bias + bf16 into stage
#pragma unroll
        for (int mi = 0; mi < 4; mi++) {
#pragma unroll
            for (int ni = 0; ni < 4; ni++) {
                int cl = wn + ni * 8 + c0;
                float bb0 = b2[bn * 128 + cl], bb1 = b2[bn * 128 + cl + 1];
                int rl = wm + mi * 16 + r0;
                __nv_bfloat162 v;
                v.x = __float2bfloat16_rn(acc[mi][ni][0] + bb0);
                v.y = __float2bfloat16_rn(acc[mi][ni][1] + bb1);
                *(__nv_bfloat162*)&stage[rl * SPAD + cl] = v;
                v.x = __float2bfloat16_rn(acc[mi][ni][2] + bb0);
                v.y = __float2bfloat16_rn(acc[mi][ni][3] + bb1);
                *(__nv_bfloat162*)&stage[(rl + 8) * SPAD + cl] = v;
            }
        }
        __syncthreads();   // stage visible to all before store

        // coalesced uint4 stores
#pragma unroll
        for (int p = 0; p < 8; p++) {
            int idx = tid + p * 256;
            int row = idx >> 4, c8 = (idx & 15) * 8;
            int grow = bm * 128 + row;
            if (grow < Ee)
                *(uint4*)&g_ewb[(size_t)grow * DDf + bn * 128 + c8] =
                    *(const uint4*)&stage[row * SPAD + c8];
        }
    }
}

// ---------------- msgagg v4: 2 warps per node (split-i), smem combine ------------
__global__ void __launch_bounds__(256) msgagg_kernel(const float* __restrict__ conv_b) {
    __shared__ float comb[4][64];
    const int warp = threadIdx.x >> 5, lane = threadIdx.x & 31;
    const int ln = warp >> 1;
    const int half = warp & 1;
    const int n = blockIdx.x * 4 + ln;
    const bool active = (n < Nn);
    const int j0 = active ? g_eoff[n] : 0;
    const int j1 = active ? g_eoff[n + 1] : 0;
    const int r = lane >> 3;
    const int c8 = (lane & 7) * 8;
    const int ibase = half * 32;
    const unsigned FULL = 0xffffffffu;
    float acc[8];
#pragma unroll
    for (int q = 0; q < 8; q++) acc[q] = 0.0f;

    int j = j0;
    for (; j + 1 < j1; j += 2) {
        int e0 = g_perm[j],   s0 = g_src[j];
        int e1 = g_perm[j+1], s1 = g_src[j+1];
        uint32_t xv0 = *((const uint32_t*)&g_mh[s0 * 128 + 64] + lane);
        uint32_t xv1 = *((const uint32_t*)&g_mh[s1 * 128 + 64] + lane);
        const __nv_bfloat16* wp0 = g_ewb + (size_t)e0 * DDf + c8;
        const __nv_bfloat16* wp1 = g_ewb + (size_t)e1 * DDf + c8;
#pragma unroll
        for (int t = 0; t < 8; t++) {
            int i = ibase + t * 4 + r;
            uint4 v0 = *(const uint4*)(wp0 + (size_t)i * 64);
            uint4 v1 = *(const uint4*)(wp1 + (size_t)i * 64);
            int sl = half * 16 + 2 * t + (r >> 1);
            uint32_t xp0 = __shfl_sync(FULL, xv0, sl);
            uint32_t xp1 = __shfl_sync(FULL, xv1, sl);
            __nv_bfloat162 xq0 = *(__nv_bfloat162*)&xp0;
            __nv_bfloat162 xq1 = *(__nv_bfloat162*)&xp1;
            float xi0 = (r & 1) ? __bfloat162float(xq0.y) : __bfloat162float(xq0.x);
            float xi1 = (r & 1) ? __bfloat162float(xq1.y) : __bfloat162float(xq1.x);
            const __nv_bfloat162* p0 = (const __nv_bfloat162*)&v0;
            const __nv_bfloat162* p1 = (const __nv_bfloat162*)&v1;
#pragma unroll
            for (int q = 0; q < 4; q++) {
                acc[2*q]   = fmaf(xi0, __bfloat162float(p0[q].x), acc[2*q]);
                acc[2*q+1] = fmaf(xi0, __bfloat162float(p0[q].y), acc[2*q+1]);
                acc[2*q]   = fmaf(xi1, __bfloat162float(p1[q].x), acc[2*q]);
                acc[2*q+1] = fmaf(xi1, __bfloat162float(p1[q].y), acc[2*q+1]);
            }
        }
    }
    if (j < j1) {
        int e0 = g_perm[j], s0 = g_src[j];
        uint32_t xv0 = *((const uint32_t*)&g_mh[s0 * 128 + 64] + lane);
        const __nv_bfloat16* wp0 = g_ewb + (size_t)e0 * DDf + c8;
#pragma unroll
        for (int t = 0; t < 8; t++) {
            int i = ibase + t * 4 + r;
            uint4 v0 = *(const uint4*)(wp0 + (size_t)i * 64);
            int sl = half * 16 + 2 * t + (r >> 1);
            uint32_t xp0 = __shfl_sync(FULL, xv0, sl);
            __nv_bfloat162 xq0 = *(__nv_bfloat162*)&xp0;
            float xi0 = (r & 1) ? __bfloat162float(xq0.y) : __bfloat162float(xq0.x);
            const __nv_bfloat162* p0 = (const __nv_bfloat162*)&v0;
#pragma unroll
            for (int q = 0; q < 4; q++) {
                acc[2*q]   = fmaf(xi0, __bfloat162float(p0[q].x), acc[2*q]);
                acc[2*q+1] = fmaf(xi0, __bfloat162float(p0[q].y), acc[2*q+1]);
            }
        }
    }
#pragma unroll
    for (int q = 0; q < 8; q++) {
        acc[q] += __shfl_xor_sync(FULL, acc[q], 8);
        acc[q] += __shfl_xor_sync(FULL, acc[q], 16);
    }
    if (half == 0 && lane < 8) {
        float4 v0 = make_float4(acc[0], acc[1], acc[2], acc[3]);
        float4 v1 = make_float4(acc[4], acc[5], acc[6], acc[7]);
        *(float4*)&comb[ln][lane * 8]     = v0;
        *(float4*)&comb[ln][lane * 8 + 4] = v1;
    }
    __syncthreads();
    if (half == 1 && lane < 8 && active) {
        float inv = g_invdeg[n];
        const float* cb = &comb[ln][lane * 8];
        __nv_bfloat16 mv[8];
#pragma unroll
        for (int q = 0; q < 8; q++) {
            float m = fmaxf(fmaf(acc[q] + cb[q], inv, conv_b[lane * 8 + q]), 0.0f);
            mv[q] = __float2bfloat16_rn(m);
        }
        *(uint4*)&g_mh[n * 128 + lane * 8] = *(const uint4*)mv;
    }
}

// ---------------- gru_v3 (measured 14us) -----------------------------------------
#define GV_AS 0
#define GV_BS 34816
#define GV_H  (34816 * 4)
#define GV_SMEM (139264 + 34816)   // 174080
__global__ void __launch_bounds__(256, 1) gru_v3(const float* __restrict__ b_ih,
                                                 const float* __restrict__ b_hh) {
    extern __shared__ __align__(16) unsigned char sm[];
    __nv_bfloat16* As = (__nv_bfloat16*)(sm + GV_AS);
    __nv_bfloat16* Bs = (__nv_bfloat16*)(sm + GV_BS);
    float* hs = (float*)(sm + GV_H);

    const int bm = blockIdx.x;
    const int tid = threadIdx.x;
    const int warp = tid >> 5, lane = tid & 31;
    const int wm = (warp >> 2) * 64;
    const int wn = (warp & 3) * 32;

#pragma unroll
    for (int u = tid; u < 2048; u += 256) {
        int r = u >> 4, c = (u & 15) * 8;
        int grow = bm * 128 + r;
        int szA = (grow < Nn) ? 16 : 0;
        cp_async16(&As[r * SPAD + c], &g_mh[(size_t)grow * 128 + c], szA);
        cp_async16(&Bs[(0 * 128 + r) * SPAD + c], &g_WcatT[(0 * 128 + r) * 128 + c], 16);
        cp_async16(&Bs[(1 * 128 + r) * SPAD + c], &g_WcatT[(1 * 128 + r) * 128 + c], 16);
        cp_async16(&Bs[(2 * 128 + r) * SPAD + c], &g_WcatT[(2 * 128 + r) * 128 + c], 16);
        int c4 = (u & 15) * 4;
        cp_async16(&hs[r * 68 + c4], &g_h[(size_t)grow * 64 + c4], szA);
    }
    cp_commit();
    cp_wait<0>();
    __syncthreads();

    const int lrow = lane & 15;
    const int lcol8 = ((lane >> 4) & 1) * 8;
    const int lbrow = lane & 7;
    const int lbcol8 = ((lane >> 3) & 1) * 8;
    const int r0 = lane >> 2;
    const int c0 = (lane & 3) * 2;

    float rgv[4][4][2], zgv[4][4][2];

#pragma unroll
    for (int ch = 0; ch < 3; ch++) {
        const __nv_bfloat16* Bc = Bs + ch * 128 * SPAD;
        float acc[4][4][4];
#pragma unroll
        for (int mi = 0; mi < 4; mi++)
#pragma unroll
            for (int ni = 0; ni < 4; ni++)
#pragma unroll
                for (int r = 0; r < 4; r++) acc[mi][ni][r] = 0.0f;

#pragma unroll
        for (int k0 = 0; k0 < 128; k0 += 16) {
            uint32_t a[4][4], b[4][2];
#pragma unroll
            for (int mi = 0; mi < 4; mi++)
                ldsm_x4(a[mi], &As[(wm + mi * 16 + lrow) * SPAD + k0 + lcol8]);
#pragma unroll
            for (int ni = 0; ni < 4; ni++)
                ldsm_x2(b[ni], &Bc[(wn + ni * 8 + lbrow) * SPAD + k0 + lbcol8]);
#pragma unroll
            for (int mi = 0; mi < 4; mi++)
#pragma unroll
                for (int ni = 0; ni < 4; ni++)
                    mma_bf16(acc[mi][ni], a[mi], b[ni]);
        }

#pragma unroll
        for (int mi = 0; mi < 4; mi++) {
#pragma unroll
            for (int ni = 0; ni < 4; ni++) {
                int d = (wn + ni * 8 + c0) >> 1;
                float bi = b_ih[ch * 64 + d];
                float bh = b_hh[ch * 64 + d];
                if (ch == 0) {
                    rgv[mi][ni][0] = sigmfast(acc[mi][ni][0] + bi + acc[mi][ni][1] + bh);
                    rgv[mi][ni][1] = sigmfast(acc[mi][ni][2] + bi + acc[mi][ni][3] + bh);
                } else if (ch == 1) {
                    zgv[mi][ni][0] = sigmfast(acc[mi][ni][0] + bi + acc[mi][ni][1] + bh);
                    zgv[mi][ni][1] = sigmfast(acc[mi][ni][2] + bi + acc[mi][ni][3] + bh);
                } else {
                    int rl = wm + mi * 16 + r0;
                    int gn0 = bm * 128 + rl;
                    if (gn0 < Nn) {
                        float ng = tanhfast(fmaf(rgv[mi][ni][0], acc[mi][ni][1] + bh,
                                                 acc[mi][ni][0] + bi));
                        float zg = zgv[mi][ni][0];
                        float hv = hs[rl * 68 + d];
                        float h = (1.0f - zg) * ng + zg * hv;
                        g_h[gn0 * 64 + d] = h;
                        g_mh[gn0 * 128 + 64 + d] = __float2bfloat16_rn(h);
                    }
                    int gn1 = gn0 + 8;
                    if (gn1 < Nn) {
                        float ng = tanhfast(fmaf(rgv[mi][ni][1], acc[mi][ni][3] + bh,
                                                 acc[mi][ni][2] + bi));
                        float zg = zgv[mi][ni][1];
                        float hv = hs[(rl + 8) * 68 + d];
                        float h = (1.0f - zg) * ng + zg * hv;
                        g_h[gn1 * 64 + d] = h;
                        g_mh[gn1 * 128 + 64 + d] = __float2bfloat16_rn(h);
                    }
                }
            }
        }
    }
}

// ---------------- fused Set2Set (6 steps) + output MLP — coalesced weights -------
__global__ void __launch_bounds__(256) set2set_kernel(
    const float* __restrict__ b_ih, const float* __restrict__ b_hh,
    const float* __restrict__ lin1_b,
    const float* __restrict__ lin2_w, const float* __restrict__ lin2_b,
    float* __restrict__ out) {
    const int b = blockIdx.x;
    const int tid = threadIdx.x;
    const int lane = tid & 31, w = tid >> 5;
    __shared__ float q[128], hl[64], cl[64], g[256];
    __shared__ float red[8];
    __shared__ float rpart[8][64];
    __shared__ float emax_s, denom_s;
    __shared__ float z[64];

    if (tid < 128) q[tid] = 0.0f;
    if (tid < 64) { hl[tid] = 0.0f; cl[tid] = 0.0f; }
    __syncthreads();

    const int s = g_boff[b], epos = g_boff[b + 1];
    const unsigned FULL = 0xffffffffu;

    for (int step = 0; step < NSTEPS; step++) {
        {
            int j = tid;
            float acc = b_ih[j] + b_hh[j];
#pragma unroll 8
            for (int k = 0; k < 128; k++)
                acc = fmaf(q[k], g_lwihT[k * 256 + j], acc);
#pragma unroll 8
            for (int k = 0; k < 64; k++)
                acc = fmaf(hl[k], g_lwhhT[k * 256 + j], acc);
            g[j] = acc;
        }
        __syncthreads();
        if (tid < 64) {
            int d = tid;
            float ig = g[d], fg = g[64 + d], gg = g[128 + d], og = g[192 + d];
            float c = sigmfast(fg) * cl[d] + sigmfast(ig) * tanhfast(gg);
            cl[d] = c;
            hl[d] = sigmfast(og) * tanhfast(c);
        }
        __syncthreads();

        float lmax = -FLT_MAX;
        for (int n = s + w; n < epos; n += 8) {
            const float* hr = g_h + n * 64;
            float v = hr[lane] * hl[lane] + hr[32 + lane] * hl[32 + lane];
#pragma unroll
            for (int off = 16; off > 0; off >>= 1) v += __shfl_down_sync(FULL, v, off);
            v = __shfl_sync(FULL, v, 0);
            lmax = fmaxf(lmax, v);
        }
        if (lane == 0) red[w] = lmax;
        __syncthreads();
        if (tid == 0) {
            float m = red[0];
#pragma unroll
            for (int i = 1; i < 8; i++) m = fmaxf(m, red[i]);
            emax_s = m;
        }
        __syncthreads();
        float emax = emax_s;

        float lsum = 0.0f, r0 = 0.0f, r1 = 0.0f;
        for (int n = s + w; n < epos; n += 8) {
            const float* hr = g_h + n * 64;
            float x0 = hr[lane], x1 = hr[32 + lane];
            float v = x0 * hl[lane] + x1 * hl[32 + lane];
#pragma unroll
            for (int off = 16; off > 0; off >>= 1) v += __shfl_down_sync(FULL, v, off);
            v = __shfl_sync(FULL, v, 0);
            float ex = __expf(v - emax);
            lsum += ex;
            r0 = fmaf(ex, x0, r0);
            r1 = fmaf(ex, x1, r1);
        }
        if (lane == 0) red[w] = lsum;
        rpart[w][lane] = r0;
        rpart[w][32 + lane] = r1;
        __syncthreads();
        if (tid == 0) {
            float ssum = 0.0f;
#pragma unroll
            for (int i = 0; i < 8; i++) ssum += red[i];
            denom_s = ssum;
        }
        __syncthreads();
        if (tid < 64) {
            float rv = 0.0f;
#pragma unroll
            for (int i = 0; i < 8; i++) rv += rpart[i][tid];
            q[64 + tid] = rv / (denom_s + 1e-16f);
            q[tid] = hl[tid];
        }
        __syncthreads();
    }

    if (tid < 64) {
        float acc = lin1_b[tid];
#pragma unroll 8
        for (int k = 0; k < 128; k++)
            acc = fmaf(q[k], g_l1T[k * 64 + tid], acc);
        z[tid] = fmaxf(acc, 0.0f);
    }
    __syncthreads();
    if (tid < 12) {
        float acc = lin2_b[tid];
        const float* wr = lin2_w + tid * 64;
#pragma unroll
        for (int d = 0; d < 64; d++) acc = fmaf(z[d], wr[d], acc);
        out[b * 12 + tid] = acc;
    }
}

// ---------------- launch ----------------
extern "C" void kernel_launch(void* const* d_in, const int* in_sizes, int n_in,
                              void* d_out, int out_size) {
    const float* x         = (const float*)d_in[0];
    const float* edge_attr = (const float*)d_in[1];
    const int*   edge_index= (const int*)  d_in[2];
    const int*   batch     = (const int*)  d_in[3];
    const float* lin0_w    = (const float*)d_in[4];
    const float* lin0_b    = (const float*)d_in[5];
    const float* en_w1     = (const float*)d_in[6];
    const float* en_b1     = (const float*)d_in[7];
    const float* en_w2     = (const float*)d_in[8];
    const float* en_b2     = (const float*)d_in[9];
    const float* conv_b    = (const float*)d_in[10];
    const float* gru_w_ih  = (const float*)d_in[11];
    const float* gru_w_hh  = (const float*)d_in[12];
    const float* gru_b_ih  = (const float*)d_in[13];
    const float* gru_b_hh  = (const float*)d_in[14];
    const float* lstm_w_ih = (const float*)d_in[15];
    const float* lstm_w_hh = (const float*)d_in[16];
    const float* lstm_b_ih = (const float*)d_in[17];
    const float* lstm_b_hh = (const float*)d_in[18];
    const float* lin1_w    = (const float*)d_in[19];
    const float* lin1_b    = (const float*)d_in[20];
    const float* lin2_w    = (const float*)d_in[21];
    const float* lin2_b    = (const float*)d_in[22];
    float* out = (float*)d_out;

    const int prep_smem = 2 * Nn * (int)sizeof(int);  // 120000
    cudaFuncSetAttribute(gemm_ew_mma, cudaFuncAttributeMaxDynamicSharedMemorySize,
                         GB_SMEM);
    cudaFuncSetAttribute(gru_v3, cudaFuncAttributeMaxDynamicSharedMemorySize,
                         GV_SMEM);
    cudaFuncSetAttribute(prep_csr_kernel, cudaFuncAttributeMaxDynamicSharedMemorySize,
                         prep_smem);

    prep_csr_kernel<<<PREP_BLOCKS, 1024, prep_smem>>>(
        x, lin0_w, lin0_b, en_w2, edge_attr, en_w1, en_b1,
        gru_w_ih, gru_w_hh, batch, edge_index,
        lstm_w_ih, lstm_w_hh, lin1_w);
    gemm_ew_mma<<<(Ee + 127) / 128, 256, GB_SMEM>>>(en_b2);

    for (int s = 0; s < NSTEPS; s++) {
        msgagg_kernel<<<(Nn + 3) / 4, 256>>>(conv_b);
        gru_v3<<<(Nn + 127) / 128, 256, GV_SMEM>>>(gru_b_ih, gru_b_hh);
    }

    set2set_kernel<<<Bb, 256>>>(lstm_b_ih, lstm_b_hh,
                                lin1_b, lin2_w, lin2_b, out);
}

// round 16
// speedup vs baseline: 1.0784x; 1.0784x over previous
#include <cuda_runtime.h>
#include <cuda_bf16.h>
#include <math.h>
#include <float.h>
#include <stdint.h>

#define Nn 15000
#define Ee 60000
#define Bb 512
#define Dd 64
#define EHh 128
#define DDf 4096   // D*D
#define NSTEPS 6
#define SPAD 136

// ---------------- device scratch ----------------
static __device__ __nv_bfloat16 g_Hb[(size_t)Ee * EHh];    // edge hidden (edge order)
static __device__ __nv_bfloat16 g_W2b[(size_t)DDf * EHh];  // en_w2 bf16 [4096,128]
static __device__ __nv_bfloat16 g_ewb[(size_t)Ee * DDf];   // edge weights (edge order)
static __device__ float g_h[Nn * Dd];                      // node state fp32 (master)
static __device__ __nv_bfloat16 g_mh[Nn * 128];            // [m | h] per node, bf16
static __device__ __nv_bfloat16 g_WcatT[384 * 128];        // interleaved GRU weights^T
static __device__ float g_invdeg[Nn];
static __device__ int   g_eoff[Nn + 1];                    // CSR offsets by target
static __device__ int   g_perm[Ee];                        // edge ids grouped by target
static __device__ int   g_src[Ee];                         // src node per CSR pos
static __device__ int   g_boff[Bb + 1];                    // batch segment offsets
static __device__ float g_lwihT[128 * 256];                // LSTM w_ih^T (k-major)
static __device__ float g_lwhhT[64 * 256];                 // LSTM w_hh^T (k-major)
static __device__ float g_l1T[128 * 64];                   // lin1_w^T (k-major)

// ---------------- helpers ----------------
__device__ __forceinline__ float tanhfast(float x) {
    float y;
    asm("tanh.approx.f32 %0, %1;" : "=f"(y) : "f"(x));
    return y;
}
__device__ __forceinline__ float sigmfast(float x) {
    return fmaf(0.5f, tanhfast(0.5f * x), 0.5f);
}

__device__ __forceinline__ void ldsm_x4(uint32_t* r, const void* p) {
    uint32_t addr = (uint32_t)__cvta_generic_to_shared(p);
    asm volatile("ldmatrix.sync.aligned.m8n8.x4.shared.b16 {%0,%1,%2,%3}, [%4];"
                 : "=r"(r[0]), "=r"(r[1]), "=r"(r[2]), "=r"(r[3]) : "r"(addr));
}
__device__ __forceinline__ void ldsm_x2(uint32_t* r, const void* p) {
    uint32_t addr = (uint32_t)__cvta_generic_to_shared(p);
    asm volatile("ldmatrix.sync.aligned.m8n8.x2.shared.b16 {%0,%1}, [%2];"
                 : "=r"(r[0]), "=r"(r[1]) : "r"(addr));
}
__device__ __forceinline__ void mma_bf16(float* c, const uint32_t* a, const uint32_t* b) {
    asm volatile(
        "mma.sync.aligned.m16n8k16.row.col.f32.bf16.bf16.f32 "
        "{%0,%1,%2,%3}, {%4,%5,%6,%7}, {%8,%9}, {%0,%1,%2,%3};"
        : "+f"(c[0]), "+f"(c[1]), "+f"(c[2]), "+f"(c[3])
        : "r"(a[0]), "r"(a[1]), "r"(a[2]), "r"(a[3]), "r"(b[0]), "r"(b[1]));
}
__device__ __forceinline__ void cp_async16(void* dst, const void* src, int sz) {
    uint32_t d = (uint32_t)__cvta_generic_to_shared(dst);
    asm volatile("cp.async.cg.shared.global [%0], [%1], 16, %2;"
                 :: "r"(d), "l"(src), "r"(sz));
}
__device__ __forceinline__ void cp_commit() { asm volatile("cp.async.commit_group;"); }
template <int N>
__device__ __forceinline__ void cp_wait() {
    asm volatile("cp.async.wait_group %0;" :: "n"(N));
}

// ---------------- merged prep + csr ----------------------------------------------
#define PA0 (Nn * Dd)
#define PA1 (DDf * EHh)
#define PA2 (Ee * EHh)
#define PA3 (384 * 128)
#define PA4 (Bb + 1)
#define PA5 (128 * 256)
#define PA6 (64 * 256)
#define PA7 (128 * 64)
#define PA_TOT (PA0 + PA1 + PA2 + PA3 + PA4 + PA5 + PA6 + PA7)
#define PREP_BLOCKS 148
__global__ void __launch_bounds__(1024) prep_csr_kernel(
    const float* __restrict__ x,
    const float* __restrict__ lw,
    const float* __restrict__ lb,
    const float* __restrict__ w2,
    const float* __restrict__ ea,
    const float* __restrict__ w1,
    const float* __restrict__ b1,
    const float* __restrict__ wih,
    const float* __restrict__ whh,
    const int* __restrict__ batch,
    const int* __restrict__ edge_index,
    const float* __restrict__ lstm_wih,
    const float* __restrict__ lstm_whh,
    const float* __restrict__ lin1_w) {
    const int t = threadIdx.x;
    if (blockIdx.x == 0) {
        extern __shared__ int sdyn[];
        int* scnt = sdyn;
        int* scur = sdyn + Nn;
        __shared__ int part[1024];
        for (int i = t; i < Nn; i += 1024) { scnt[i] = 0; scur[i] = 0; }
        __syncthreads();
        for (int e = t; e < Ee; e += 1024)
            atomicAdd(&scnt[edge_index[Ee + e]], 1);
        __syncthreads();
        int loc[15];
        int s = 0;
#pragma unroll
        for (int j = 0; j < 15; j++) {
            int idx = t * 15 + j;
            int v = (idx < Nn) ? scnt[idx] : 0;
            loc[j] = s; s += v;
        }
        part[t] = s;
        __syncthreads();
        for (int off = 1; off < 1024; off <<= 1) {
            int v = (t >= off) ? part[t - off] : 0;
            __syncthreads();
            part[t] += v;
            __syncthreads();
        }
        int excl = part[t] - s;
#pragma unroll
        for (int j = 0; j < 15; j++) {
            int idx = t * 15 + j;
            if (idx < Nn) {
                g_eoff[idx] = excl + loc[j];
                g_invdeg[idx] = 1.0f / fmaxf((float)scnt[idx], 1.0f);
            }
        }
        if (t == 0) g_eoff[Nn] = Ee;
        __syncthreads();
        for (int e = t; e < Ee; e += 1024) {
            int tgt = edge_index[Ee + e];
            int pos = atomicAdd(&scur[tgt], 1);
            int base = g_eoff[tgt] + pos;
            g_perm[base] = e;
            g_src[base] = edge_index[e];
        }
        return;
    }
    const int stride = (PREP_BLOCKS - 1) * 1024;
    for (int idx = (blockIdx.x - 1) * 1024 + t; idx < PA_TOT; idx += stride) {
        if (idx < PA0) {
            int n = idx >> 6, o = idx & 63;
            float acc = lb[o];
            const float* xr = x + n * 15;
            const float* wr = lw + o * 15;
#pragma unroll
            for (int j = 0; j < 15; j++) acc = fmaf(xr[j], wr[j], acc);
            float h = fmaxf(acc, 0.0f);
            g_h[idx] = h;
            g_mh[n * 128 + 64 + o] = __float2bfloat16_rn(h);
        } else if (idx < PA0 + PA1) {
            int q = idx - PA0;
            g_W2b[q] = __float2bfloat16_rn(w2[q]);
        } else if (idx < PA0 + PA1 + PA2) {
            int q = idx - PA0 - PA1;
            int e = q >> 7, k = q & 127;
            float acc = b1[k];
            const float* er = ea + e * 5;
            const float* wr = w1 + k * 5;
#pragma unroll
            for (int j = 0; j < 5; j++) acc = fmaf(er[j], wr[j], acc);
            g_Hb[q] = __float2bfloat16_rn(fmaxf(acc, 0.0f));
        } else if (idx < PA0 + PA1 + PA2 + PA3) {
            int q = idx - PA0 - PA1 - PA2;
            int jf = q >> 7, k = q & 127;
            int ch = jf >> 7;
            int j = jf & 127;
            int d = j >> 1;
            float v = 0.0f;
            if ((j & 1) == 0) { if (k < 64)  v = wih[(ch * 64 + d) * 64 + k]; }
            else              { if (k >= 64) v = whh[(ch * 64 + d) * 64 + (k - 64)]; }
            g_WcatT[jf * 128 + k] = __float2bfloat16_rn(v);
        } else if (idx < PA0 + PA1 + PA2 + PA3 + PA4) {
            int b = idx - PA0 - PA1 - PA2 - PA3;
            int lo = 0, hi = Nn;
            while (lo < hi) {
                int mid = (lo + hi) >> 1;
                if (batch[mid] < b) lo = mid + 1; else hi = mid;
            }
            g_boff[b] = lo;
        } else if (idx < PA0 + PA1 + PA2 + PA3 + PA4 + PA5) {
            int q = idx - PA0 - PA1 - PA2 - PA3 - PA4;
            int k = q >> 8, j = q & 255;
            g_lwihT[q] = lstm_wih[j * 128 + k];
        } else if (idx < PA0 + PA1 + PA2 + PA3 + PA4 + PA5 + PA6) {
            int q = idx - PA0 - PA1 - PA2 - PA3 - PA4 - PA5;
            int k = q >> 8, j = q & 255;
            g_lwhhT[q] = lstm_whh[j * 64 + k];
        } else {
            int q = idx - PA0 - PA1 - PA2 - PA3 - PA4 - PA5 - PA6;
            int k = q >> 6, j = q & 63;
            g_l1T[q] = lin1_w[j * 128 + k];
        }
    }
}

// ---------------- ew GEMM (R13 structure + paired-B ldsm_x4) ---------------------
// Block tile 128x128, full K=128 in smem, 2 blocks/SM, 15008 blocks.
// Per k-step: 4 ldsm_x4 (A) + 2 ldsm_x4 (B pairs) = 6 LDSM (was 8).
__global__ void __launch_bounds__(256) gemm_ew_mma(const float* __restrict__ b2) {
    extern __shared__ __align__(16) __nv_bfloat16 smem[];
    __nv_bfloat16* As = smem;
    __nv_bfloat16* Bs = smem + 128 * SPAD;

    const int bm = blockIdx.y;
    const int bn = blockIdx.x;
    const int tid = threadIdx.x;
    const int warp = tid >> 5, lane = tid & 31;
    const int wm = (warp >> 2) * 64;
    const int wn = (warp & 3) * 32;

#pragma unroll
    for (int u = tid; u < 2048; u += 256) {
        int r = u >> 4, c = (u & 15) * 8;
        int grow = bm * 128 + r;
        cp_async16(&As[r * SPAD + c], &g_Hb[(size_t)grow * 128 + c],
                   (grow < Ee) ? 16 : 0);
        cp_async16(&Bs[r * SPAD + c], &g_W2b[(size_t)(bn * 128 + r) * 128 + c], 16);
    }
    cp_commit();
    cp_wait<0>();
    __syncthreads();

    float acc[4][4][4];
#pragma unroll
    for (int mi = 0; mi < 4; mi++)
#pragma unroll
        for (int ni = 0; ni < 4; ni++)
#pragma unroll
            for (int r = 0; r < 4; r++) acc[mi][ni][r] = 0.0f;

    const int lrow = lane & 15;
    const int lcol8 = ((lane >> 4) & 1) * 8;
    // paired-B x4: lanes 0-7 -> ni0/k-lo, 8-15 -> ni0/k-hi, 16-23 -> ni1/k-lo,
    // 24-31 -> ni1/k-hi
    const int pbrow = (lane & 7) + ((lane >> 4) & 1) * 8;
    const int pbcol8 = ((lane >> 3) & 1) * 8;

#pragma unroll
    for (int k0 = 0; k0 < 128; k0 += 16) {
        uint32_t a[4][4], b[2][4];
#pragma unroll
        for (int mi = 0; mi < 4; mi++)
            ldsm_x4(a[mi], &As[(wm + mi * 16 + lrow) * SPAD + k0 + lcol8]);
#pragma unroll
        for (int p = 0; p < 2; p++)
            ldsm_x4(b[p], &Bs[(wn + p * 16 + pbrow) * SPAD + k0 + pbcol8]);
#pragma unroll
        for (int mi = 0; mi < 4; mi++)
#pragma unroll
            for (int ni = 0; ni < 4; ni++)
                mma_bf16(acc[mi][ni], a[mi], &b[ni >> 1][(ni & 1) * 2]);
    }
    __syncthreads();

    __nv_bfloat16* stage = As;
    const int r0 = lane >> 2;
    const int c0 = (lane & 3) * 2;
#pragma unroll
    for (int mi = 0; mi < 4; mi++) {
#pragma unroll
        for (int ni = 0; ni < 4; ni++) {
            int cl = wn + ni * 8 + c0;
            float bb0 = b2[bn * 128 + cl], bb1 = b2[bn * 128 + cl + 1];
            int rl = wm + mi * 16 + r0;
            __nv_bfloat162 v;
            v.x = __float2bfloat16_rn(acc[mi][ni][0] + bb0);
            v.y = __float2bfloat16_rn(acc[mi][ni][1] + bb1);
            *(__nv_bfloat162*)&stage[rl * SPAD + cl] = v;
            v.x = __float2bfloat16_rn(acc[mi][ni][2] + bb0);
            v.y = __float2bfloat16_rn(acc[mi][ni][3] + bb1);
            *(__nv_bfloat162*)&stage[(rl + 8) * SPAD + cl] = v;
        }
    }
    __syncthreads();
#pragma unroll
    for (int p = 0; p < 8; p++) {
        int idx = tid + p * 256;
        int row = idx >> 4, c8 = (idx & 15) * 8;
        int grow = bm * 128 + row;
        if (grow < Ee)
            *(uint4*)&g_ewb[(size_t)grow * DDf + bn * 128 + c8] =
                *(const uint4*)&stage[row * SPAD + c8];
    }
}

// ---------------- msgagg v4: 2 warps per node (split-i), smem combine ------------
__global__ void __launch_bounds__(256) msgagg_kernel(const float* __restrict__ conv_b) {
    __shared__ float comb[4][64];
    const int warp = threadIdx.x >> 5, lane = threadIdx.x & 31;
    const int ln = warp >> 1;
    const int half = warp & 1;
    const int n = blockIdx.x * 4 + ln;
    const bool active = (n < Nn);
    const int j0 = active ? g_eoff[n] : 0;
    const int j1 = active ? g_eoff[n + 1] : 0;
    const int r = lane >> 3;
    const int c8 = (lane & 7) * 8;
    const int ibase = half * 32;
    const unsigned FULL = 0xffffffffu;
    float acc[8];
#pragma unroll
    for (int q = 0; q < 8; q++) acc[q] = 0.0f;

    int j = j0;
    for (; j + 1 < j1; j += 2) {
        int e0 = g_perm[j],   s0 = g_src[j];
        int e1 = g_perm[j+1], s1 = g_src[j+1];
        uint32_t xv0 = *((const uint32_t*)&g_mh[s0 * 128 + 64] + lane);
        uint32_t xv1 = *((const uint32_t*)&g_mh[s1 * 128 + 64] + lane);
        const __nv_bfloat16* wp0 = g_ewb + (size_t)e0 * DDf + c8;
        const __nv_bfloat16* wp1 = g_ewb + (size_t)e1 * DDf + c8;
#pragma unroll
        for (int t = 0; t < 8; t++) {
            int i = ibase + t * 4 + r;
            uint4 v0 = *(const uint4*)(wp0 + (size_t)i * 64);
            uint4 v1 = *(const uint4*)(wp1 + (size_t)i * 64);
            int sl = half * 16 + 2 * t + (r >> 1);
            uint32_t xp0 = __shfl_sync(FULL, xv0, sl);
            uint32_t xp1 = __shfl_sync(FULL, xv1, sl);
            __nv_bfloat162 xq0 = *(__nv_bfloat162*)&xp0;
            __nv_bfloat162 xq1 = *(__nv_bfloat162*)&xp1;
            float xi0 = (r & 1) ? __bfloat162float(xq0.y) : __bfloat162float(xq0.x);
            float xi1 = (r & 1) ? __bfloat162float(xq1.y) : __bfloat162float(xq1.x);
            const __nv_bfloat162* p0 = (const __nv_bfloat162*)&v0;
            const __nv_bfloat162* p1 = (const __nv_bfloat162*)&v1;
#pragma unroll
            for (int q = 0; q < 4; q++) {
                acc[2*q]   = fmaf(xi0, __bfloat162float(p0[q].x), acc[2*q]);
                acc[2*q+1] = fmaf(xi0, __bfloat162float(p0[q].y), acc[2*q+1]);
                acc[2*q]   = fmaf(xi1, __bfloat162float(p1[q].x), acc[2*q]);
                acc[2*q+1] = fmaf(xi1, __bfloat162float(p1[q].y), acc[2*q+1]);
            }
        }
    }
    if (j < j1) {
        int e0 = g_perm[j], s0 = g_src[j];
        uint32_t xv0 = *((const uint32_t*)&g_mh[s0 * 128 + 64] + lane);
        const __nv_bfloat16* wp0 = g_ewb + (size_t)e0 * DDf + c8;
#pragma unroll
        for (int t = 0; t < 8; t++) {
            int i = ibase + t * 4 + r;
            uint4 v0 = *(const uint4*)(wp0 + (size_t)i * 64);
            int sl = half * 16 + 2 * t + (r >> 1);
            uint32_t xp0 = __shfl_sync(FULL, xv0, sl);
            __nv_bfloat162 xq0 = *(__nv_bfloat162*)&xp0;
            float xi0 = (r & 1) ? __bfloat162float(xq0.y) : __bfloat162float(xq0.x);
            const __nv_bfloat162* p0 = (const __nv_bfloat162*)&v0;
#pragma unroll
            for (int q = 0; q < 4; q++) {
                acc[2*q]   = fmaf(xi0, __bfloat162float(p0[q].x), acc[2*q]);
                acc[2*q+1] = fmaf(xi0, __bfloat162float(p0[q].y), acc[2*q+1]);
            }
        }
    }
#pragma unroll
    for (int q = 0; q < 8; q++) {
        acc[q] += __shfl_xor_sync(FULL, acc[q], 8);
        acc[q] += __shfl_xor_sync(FULL, acc[q], 16);
    }
    if (half == 0 && lane < 8) {
        float4 v0 = make_float4(acc[0], acc[1], acc[2], acc[3]);
        float4 v1 = make_float4(acc[4], acc[5], acc[6], acc[7]);
        *(float4*)&comb[ln][lane * 8]     = v0;
        *(float4*)&comb[ln][lane * 8 + 4] = v1;
    }
    __syncthreads();
    if (half == 1 && lane < 8 && active) {
        float inv = g_invdeg[n];
        const float* cb = &comb[ln][lane * 8];
        __nv_bfloat16 mv[8];
#pragma unroll
        for (int q = 0; q < 8; q++) {
            float m = fmaxf(fmaf(acc[q] + cb[q], inv, conv_b[lane * 8 + q]), 0.0f);
            mv[q] = __float2bfloat16_rn(m);
        }
        *(uint4*)&g_mh[n * 128 + lane * 8] = *(const uint4*)mv;
    }
}

// ---------------- gru_v3 (measured 14us) -----------------------------------------
#define GV_AS 0
#define GV_BS 34816
#define GV_H  (34816 * 4)
#define GV_SMEM (139264 + 34816)   // 174080
__global__ void __launch_bounds__(256, 1) gru_v3(const float* __restrict__ b_ih,
                                                 const float* __restrict__ b_hh) {
    extern __shared__ __align__(16) unsigned char sm[];
    __nv_bfloat16* As = (__nv_bfloat16*)(sm + GV_AS);
    __nv_bfloat16* Bs = (__nv_bfloat16*)(sm + GV_BS);
    float* hs = (float*)(sm + GV_H);

    const int bm = blockIdx.x;
    const int tid = threadIdx.x;
    const int warp = tid >> 5, lane = tid & 31;
    const int wm = (warp >> 2) * 64;
    const int wn = (warp & 3) * 32;

#pragma unroll
    for (int u = tid; u < 2048; u += 256) {
        int r = u >> 4, c = (u & 15) * 8;
        int grow = bm * 128 + r;
        int szA = (grow < Nn) ? 16 : 0;
        cp_async16(&As[r * SPAD + c], &g_mh[(size_t)grow * 128 + c], szA);
        cp_async16(&Bs[(0 * 128 + r) * SPAD + c], &g_WcatT[(0 * 128 + r) * 128 + c], 16);
        cp_async16(&Bs[(1 * 128 + r) * SPAD + c], &g_WcatT[(1 * 128 + r) * 128 + c], 16);
        cp_async16(&Bs[(2 * 128 + r) * SPAD + c], &g_WcatT[(2 * 128 + r) * 128 + c], 16);
        int c4 = (u & 15) * 4;
        cp_async16(&hs[r * 68 + c4], &g_h[(size_t)grow * 64 + c4], szA);
    }
    cp_commit();
    cp_wait<0>();
    __syncthreads();

    const int lrow = lane & 15;
    const int lcol8 = ((lane >> 4) & 1) * 8;
    const int lbrow = lane & 7;
    const int lbcol8 = ((lane >> 3) & 1) * 8;
    const int r0 = lane >> 2;
    const int c0 = (lane & 3) * 2;

    float rgv[4][4][2], zgv[4][4][2];

#pragma unroll
    for (int ch = 0; ch < 3; ch++) {
        const __nv_bfloat16* Bc = Bs + ch * 128 * SPAD;
        float acc[4][4][4];
#pragma unroll
        for (int mi = 0; mi < 4; mi++)
#pragma unroll
            for (int ni = 0; ni < 4; ni++)
#pragma unroll
                for (int r = 0; r < 4; r++) acc[mi][ni][r] = 0.0f;

#pragma unroll
        for (int k0 = 0; k0 < 128; k0 += 16) {
            uint32_t a[4][4], b[4][2];
#pragma unroll
            for (int mi = 0; mi < 4; mi++)
                ldsm_x4(a[mi], &As[(wm + mi * 16 + lrow) * SPAD + k0 + lcol8]);
#pragma unroll
            for (int ni = 0; ni < 4; ni++)
                ldsm_x2(b[ni], &Bc[(wn + ni * 8 + lbrow) * SPAD + k0 + lbcol8]);
#pragma unroll
            for (int mi = 0; mi < 4; mi++)
#pragma unroll
                for (int ni = 0; ni < 4; ni++)
                    mma_bf16(acc[mi][ni], a[mi], b[ni]);
        }

#pragma unroll
        for (int mi = 0; mi < 4; mi++) {
#pragma unroll
            for (int ni = 0; ni < 4; ni++) {
                int d = (wn + ni * 8 + c0) >> 1;
                float bi = b_ih[ch * 64 + d];
                float bh = b_hh[ch * 64 + d];
                if (ch == 0) {
                    rgv[mi][ni][0] = sigmfast(acc[mi][ni][0] + bi + acc[mi][ni][1] + bh);
                    rgv[mi][ni][1] = sigmfast(acc[mi][ni][2] + bi + acc[mi][ni][3] + bh);
                } else if (ch == 1) {
                    zgv[mi][ni][0] = sigmfast(acc[mi][ni][0] + bi + acc[mi][ni][1] + bh);
                    zgv[mi][ni][1] = sigmfast(acc[mi][ni][2] + bi + acc[mi][ni][3] + bh);
                } else {
                    int rl = wm + mi * 16 + r0;
                    int gn0 = bm * 128 + rl;
                    if (gn0 < Nn) {
                        float ng = tanhfast(fmaf(rgv[mi][ni][0], acc[mi][ni][1] + bh,
                                                 acc[mi][ni][0] + bi));
                        float zg = zgv[mi][ni][0];
                        float hv = hs[rl * 68 + d];
                        float h = (1.0f - zg) * ng + zg * hv;
                        g_h[gn0 * 64 + d] = h;
                        g_mh[gn0 * 128 + 64 + d] = __float2bfloat16_rn(h);
                    }
                    int gn1 = gn0 + 8;
                    if (gn1 < Nn) {
                        float ng = tanhfast(fmaf(rgv[mi][ni][1], acc[mi][ni][3] + bh,
                                                 acc[mi][ni][2] + bi));
                        float zg = zgv[mi][ni][1];
                        float hv = hs[(rl + 8) * 68 + d];
                        float h = (1.0f - zg) * ng + zg * hv;
                        g_h[gn1 * 64 + d] = h;
                        g_mh[gn1 * 128 + 64 + d] = __float2bfloat16_rn(h);
                    }
                }
            }
        }
    }
}

// ---------------- fused Set2Set (6 steps) + output MLP — coalesced weights -------
__global__ void __launch_bounds__(256) set2set_kernel(
    const float* __restrict__ b_ih, const float* __restrict__ b_hh,
    const float* __restrict__ lin1_b,
    const float* __restrict__ lin2_w, const float* __restrict__ lin2_b,
    float* __restrict__ out) {
    const int b = blockIdx.x;
    const int tid = threadIdx.x;
    const int lane = tid & 31, w = tid >> 5;
    __shared__ float q[128], hl[64], cl[64], g[256];
    __shared__ float red[8];
    __shared__ float rpart[8][64];
    __shared__ float emax_s, denom_s;
    __shared__ float z[64];

    if (tid < 128) q[tid] = 0.0f;
    if (tid < 64) { hl[tid] = 0.0f; cl[tid] = 0.0f; }
    __syncthreads();

    const int s = g_boff[b], epos = g_boff[b + 1];
    const unsigned FULL = 0xffffffffu;

    for (int step = 0; step < NSTEPS; step++) {
        {
            int j = tid;
            float acc = b_ih[j] + b_hh[j];
#pragma unroll 8
            for (int k = 0; k < 128; k++)
                acc = fmaf(q[k], g_lwihT[k * 256 + j], acc);
#pragma unroll 8
            for (int k = 0; k < 64; k++)
                acc = fmaf(hl[k], g_lwhhT[k * 256 + j], acc);
            g[j] = acc;
        }
        __syncthreads();
        if (tid < 64) {
            int d = tid;
            float ig = g[d], fg = g[64 + d], gg = g[128 + d], og = g[192 + d];
            float c = sigmfast(fg) * cl[d] + sigmfast(ig) * tanhfast(gg);
            cl[d] = c;
            hl[d] = sigmfast(og) * tanhfast(c);
        }
        __syncthreads();

        float lmax = -FLT_MAX;
        for (int n = s + w; n < epos; n += 8) {
            const float* hr = g_h + n * 64;
            float v = hr[lane] * hl[lane] + hr[32 + lane] * hl[32 + lane];
#pragma unroll
            for (int off = 16; off > 0; off >>= 1) v += __shfl_down_sync(FULL, v, off);
            v = __shfl_sync(FULL, v, 0);
            lmax = fmaxf(lmax, v);
        }
        if (lane == 0) red[w] = lmax;
        __syncthreads();
        if (tid == 0) {
            float m = red[0];
#pragma unroll
            for (int i = 1; i < 8; i++) m = fmaxf(m, red[i]);
            emax_s = m;
        }
        __syncthreads();
        float emax = emax_s;

        float lsum = 0.0f, r0 = 0.0f, r1 = 0.0f;
        for (int n = s + w; n < epos; n += 8) {
            const float* hr = g_h + n * 64;
            float x0 = hr[lane], x1 = hr[32 + lane];
            float v = x0 * hl[lane] + x1 * hl[32 + lane];
#pragma unroll
            for (int off = 16; off > 0; off >>= 1) v += __shfl_down_sync(FULL, v, off);
            v = __shfl_sync(FULL, v, 0);
            float ex = __expf(v - emax);
            lsum += ex;
            r0 = fmaf(ex, x0, r0);
            r1 = fmaf(ex, x1, r1);
        }
        if (lane == 0) red[w] = lsum;
        rpart[w][lane] = r0;
        rpart[w][32 + lane] = r1;
        __syncthreads();
        if (tid == 0) {
            float ssum = 0.0f;
#pragma unroll
            for (int i = 0; i < 8; i++) ssum += red[i];
            denom_s = ssum;
        }
        __syncthreads();
        if (tid < 64) {
            float rv = 0.0f;
#pragma unroll
            for (int i = 0; i < 8; i++) rv += rpart[i][tid];
            q[64 + tid] = rv / (denom_s + 1e-16f);
            q[tid] = hl[tid];
        }
        __syncthreads();
    }

    if (tid < 64) {
        float acc = lin1_b[tid];
#pragma unroll 8
        for (int k = 0; k < 128; k++)
            acc = fmaf(q[k], g_l1T[k * 64 + tid], acc);
        z[tid] = fmaxf(acc, 0.0f);
    }
    __syncthreads();
    if (tid < 12) {
        float acc = lin2_b[tid];
        const float* wr = lin2_w + tid * 64;
#pragma unroll
        for (int d = 0; d < 64; d++) acc = fmaf(z[d], wr[d], acc);
        out[b * 12 + tid] = acc;
    }
}

// ---------------- launch ----------------
extern "C" void kernel_launch(void* const* d_in, const int* in_sizes, int n_in,
                              void* d_out, int out_size) {
    const float* x         = (const float*)d_in[0];
    const float* edge_attr = (const float*)d_in[1];
    const int*   edge_index= (const int*)  d_in[2];
    const int*   batch     = (const int*)  d_in[3];
    const float* lin0_w    = (const float*)d_in[4];
    const float* lin0_b    = (const float*)d_in[5];
    const float* en_w1     = (const float*)d_in[6];
    const float* en_b1     = (const float*)d_in[7];
    const float* en_w2     = (const float*)d_in[8];
    const float* en_b2     = (const float*)d_in[9];
    const float* conv_b    = (const float*)d_in[10];
    const float* gru_w_ih  = (const float*)d_in[11];
    const float* gru_w_hh  = (const float*)d_in[12];
    const float* gru_b_ih  = (const float*)d_in[13];
    const float* gru_b_hh  = (const float*)d_in[14];
    const float* lstm_w_ih = (const float*)d_in[15];
    const float* lstm_w_hh = (const float*)d_in[16];
    const float* lstm_b_ih = (const float*)d_in[17];
    const float* lstm_b_hh = (const float*)d_in[18];
    const float* lin1_w    = (const float*)d_in[19];
    const float* lin1_b    = (const float*)d_in[20];
    const float* lin2_w    = (const float*)d_in[21];
    const float* lin2_b    = (const float*)d_in[22];
    float* out = (float*)d_out;

    const int gemm_smem = 2 * 128 * SPAD * (int)sizeof(__nv_bfloat16);  // 69632
    const int prep_smem = 2 * Nn * (int)sizeof(int);                    // 120000
    cudaFuncSetAttribute(gemm_ew_mma, cudaFuncAttributeMaxDynamicSharedMemorySize,
                         gemm_smem);
    cudaFuncSetAttribute(gru_v3, cudaFuncAttributeMaxDynamicSharedMemorySize,
                         GV_SMEM);
    cudaFuncSetAttribute(prep_csr_kernel, cudaFuncAttributeMaxDynamicSharedMemorySize,
                         prep_smem);

    prep_csr_kernel<<<PREP_BLOCKS, 1024, prep_smem>>>(
        x, lin0_w, lin0_b, en_w2, edge_attr, en_w1, en_b1,
        gru_w_ih, gru_w_hh, batch, edge_index,
        lstm_w_ih, lstm_w_hh, lin1_w);
    dim3 gemm_grid(DDf / 128, (Ee + 127) / 128);
    gemm_ew_mma<<<gemm_grid, 256, gemm_smem>>>(en_b2);

    for (int s = 0; s < NSTEPS; s++) {
        msgagg_kernel<<<(Nn + 3) / 4, 256>>>(conv_b);
        gru_v3<<<(Nn + 127) / 128, 256, GV_SMEM>>>(gru_b_ih, gru_b_hh);
    }

    set2set_kernel<<<Bb, 256>>>(lstm_b_ih, lstm_b_hh,
                                lin1_b, lin2_w, lin2_b, out);
}

// round 17
// speedup vs baseline: 1.0980x; 1.0182x over previous
#include <cuda_runtime.h>
#include <cuda_bf16.h>
#include <math.h>
#include <float.h>
#include <stdint.h>

#define Nn 15000
#define Ee 60000
#define Bb 512
#define Dd 64
#define EHh 128
#define DDf 4096   // D*D
#define NSTEPS 6
#define SPAD 136

// ---------------- device scratch ----------------
static __device__ __nv_bfloat16 g_Hb[(size_t)Ee * EHh];    // edge hidden (edge order)
static __device__ __nv_bfloat16 g_W2b[(size_t)DDf * EHh];  // en_w2 bf16 [4096,128]
static __device__ __nv_bfloat16 g_ewb[(size_t)Ee * DDf];   // edge weights (edge order)
static __device__ float g_h[Nn * Dd];                      // node state fp32 (master)
static __device__ __nv_bfloat16 g_mh[Nn * 128];            // [m | h] per node, bf16
static __device__ __nv_bfloat16 g_WcatT[384 * 128];        // interleaved GRU weights^T
static __device__ float g_invdeg[Nn];
static __device__ int   g_eoff[Nn + 1];                    // CSR offsets by target
static __device__ int   g_perm[Ee];                        // edge ids grouped by target
static __device__ int   g_src[Ee];                         // src node per CSR pos
static __device__ int   g_boff[Bb + 1];                    // batch segment offsets
static __device__ float g_lwihT[128 * 256];                // LSTM w_ih^T (k-major)
static __device__ float g_lwhhT[64 * 256];                 // LSTM w_hh^T (k-major)
static __device__ float g_l1T[128 * 64];                   // lin1_w^T (k-major)

// ---------------- helpers ----------------
__device__ __forceinline__ float tanhfast(float x) {
    float y;
    asm("tanh.approx.f32 %0, %1;" : "=f"(y) : "f"(x));
    return y;
}
__device__ __forceinline__ float sigmfast(float x) {
    return fmaf(0.5f, tanhfast(0.5f * x), 0.5f);
}

__device__ __forceinline__ void ldsm_x4(uint32_t* r, const void* p) {
    uint32_t addr = (uint32_t)__cvta_generic_to_shared(p);
    asm volatile("ldmatrix.sync.aligned.m8n8.x4.shared.b16 {%0,%1,%2,%3}, [%4];"
                 : "=r"(r[0]), "=r"(r[1]), "=r"(r[2]), "=r"(r[3]) : "r"(addr));
}
__device__ __forceinline__ void ldsm_x2(uint32_t* r, const void* p) {
    uint32_t addr = (uint32_t)__cvta_generic_to_shared(p);
    asm volatile("ldmatrix.sync.aligned.m8n8.x2.shared.b16 {%0,%1}, [%2];"
                 : "=r"(r[0]), "=r"(r[1]) : "r"(addr));
}
__device__ __forceinline__ void mma_bf16(float* c, const uint32_t* a, const uint32_t* b) {
    asm volatile(
        "mma.sync.aligned.m16n8k16.row.col.f32.bf16.bf16.f32 "
        "{%0,%1,%2,%3}, {%4,%5,%6,%7}, {%8,%9}, {%0,%1,%2,%3};"
        : "+f"(c[0]), "+f"(c[1]), "+f"(c[2]), "+f"(c[3])
        : "r"(a[0]), "r"(a[1]), "r"(a[2]), "r"(a[3]), "r"(b[0]), "r"(b[1]));
}
__device__ __forceinline__ void cp_async16(void* dst, const void* src, int sz) {
    uint32_t d = (uint32_t)__cvta_generic_to_shared(dst);
    asm volatile("cp.async.cg.shared.global [%0], [%1], 16, %2;"
                 :: "r"(d), "l"(src), "r"(sz));
}
__device__ __forceinline__ void cp_commit() { asm volatile("cp.async.commit_group;"); }
template <int N>
__device__ __forceinline__ void cp_wait() {
    asm volatile("cp.async.wait_group %0;" :: "n"(N));
}

// ---------------- merged prep + csr ----------------------------------------------
#define PA0 (Nn * Dd)
#define PA1 (DDf * EHh)
#define PA2 (Ee * EHh)
#define PA3 (384 * 128)
#define PA4 (Bb + 1)
#define PA5 (128 * 256)
#define PA6 (64 * 256)
#define PA7 (128 * 64)
#define PA_TOT (PA0 + PA1 + PA2 + PA3 + PA4 + PA5 + PA6 + PA7)
#define PREP_BLOCKS 148
__global__ void __launch_bounds__(1024) prep_csr_kernel(
    const float* __restrict__ x,
    const float* __restrict__ lw,
    const float* __restrict__ lb,
    const float* __restrict__ w2,
    const float* __restrict__ ea,
    const float* __restrict__ w1,
    const float* __restrict__ b1,
    const float* __restrict__ wih,
    const float* __restrict__ whh,
    const int* __restrict__ batch,
    const int* __restrict__ edge_index,
    const float* __restrict__ lstm_wih,
    const float* __restrict__ lstm_whh,
    const float* __restrict__ lin1_w) {
    const int t = threadIdx.x;
    if (blockIdx.x == 0) {
        extern __shared__ int sdyn[];
        int* scnt = sdyn;
        int* scur = sdyn + Nn;
        __shared__ int part[1024];
        for (int i = t; i < Nn; i += 1024) { scnt[i] = 0; scur[i] = 0; }
        __syncthreads();
        for (int e = t; e < Ee; e += 1024)
            atomicAdd(&scnt[edge_index[Ee + e]], 1);
        __syncthreads();
        int loc[15];
        int s = 0;
#pragma unroll
        for (int j = 0; j < 15; j++) {
            int idx = t * 15 + j;
            int v = (idx < Nn) ? scnt[idx] : 0;
            loc[j] = s; s += v;
        }
        part[t] = s;
        __syncthreads();
        for (int off = 1; off < 1024; off <<= 1) {
            int v = (t >= off) ? part[t - off] : 0;
            __syncthreads();
            part[t] += v;
            __syncthreads();
        }
        int excl = part[t] - s;
#pragma unroll
        for (int j = 0; j < 15; j++) {
            int idx = t * 15 + j;
            if (idx < Nn) {
                g_eoff[idx] = excl + loc[j];
                g_invdeg[idx] = 1.0f / fmaxf((float)scnt[idx], 1.0f);
            }
        }
        if (t == 0) g_eoff[Nn] = Ee;
        __syncthreads();
        for (int e = t; e < Ee; e += 1024) {
            int tgt = edge_index[Ee + e];
            int pos = atomicAdd(&scur[tgt], 1);
            int base = g_eoff[tgt] + pos;
            g_perm[base] = e;
            g_src[base] = edge_index[e];
        }
        return;
    }
    const int stride = (PREP_BLOCKS - 1) * 1024;
    for (int idx = (blockIdx.x - 1) * 1024 + t; idx < PA_TOT; idx += stride) {
        if (idx < PA0) {
            int n = idx >> 6, o = idx & 63;
            float acc = lb[o];
            const float* xr = x + n * 15;
            const float* wr = lw + o * 15;
#pragma unroll
            for (int j = 0; j < 15; j++) acc = fmaf(xr[j], wr[j], acc);
            float h = fmaxf(acc, 0.0f);
            g_h[idx] = h;
            g_mh[n * 128 + 64 + o] = __float2bfloat16_rn(h);
        } else if (idx < PA0 + PA1) {
            int q = idx - PA0;
            g_W2b[q] = __float2bfloat16_rn(w2[q]);
        } else if (idx < PA0 + PA1 + PA2) {
            int q = idx - PA0 - PA1;
            int e = q >> 7, k = q & 127;
            float acc = b1[k];
            const float* er = ea + e * 5;
            const float* wr = w1 + k * 5;
#pragma unroll
            for (int j = 0; j < 5; j++) acc = fmaf(er[j], wr[j], acc);
            g_Hb[q] = __float2bfloat16_rn(fmaxf(acc, 0.0f));
        } else if (idx < PA0 + PA1 + PA2 + PA3) {
            int q = idx - PA0 - PA1 - PA2;
            int jf = q >> 7, k = q & 127;
            int ch = jf >> 7;
            int j = jf & 127;
            int d = j >> 1;
            float v = 0.0f;
            if ((j & 1) == 0) { if (k < 64)  v = wih[(ch * 64 + d) * 64 + k]; }
            else              { if (k >= 64) v = whh[(ch * 64 + d) * 64 + (k - 64)]; }
            g_WcatT[jf * 128 + k] = __float2bfloat16_rn(v);
        } else if (idx < PA0 + PA1 + PA2 + PA3 + PA4) {
            int b = idx - PA0 - PA1 - PA2 - PA3;
            int lo = 0, hi = Nn;
            while (lo < hi) {
                int mid = (lo + hi) >> 1;
                if (batch[mid] < b) lo = mid + 1; else hi = mid;
            }
            g_boff[b] = lo;
        } else if (idx < PA0 + PA1 + PA2 + PA3 + PA4 + PA5) {
            int q = idx - PA0 - PA1 - PA2 - PA3 - PA4;
            int k = q >> 8, j = q & 255;
            g_lwihT[q] = lstm_wih[j * 128 + k];
        } else if (idx < PA0 + PA1 + PA2 + PA3 + PA4 + PA5 + PA6) {
            int q = idx - PA0 - PA1 - PA2 - PA3 - PA4 - PA5;
            int k = q >> 8, j = q & 255;
            g_lwhhT[q] = lstm_whh[j * 64 + k];
        } else {
            int q = idx - PA0 - PA1 - PA2 - PA3 - PA4 - PA5 - PA6;
            int k = q >> 6, j = q & 63;
            g_l1T[q] = lin1_w[j * 128 + k];
        }
    }
}

// ---------------- ew GEMM (R16, tied-best) ---------------------------------------
__global__ void __launch_bounds__(256) gemm_ew_mma(const float* __restrict__ b2) {
    extern __shared__ __align__(16) __nv_bfloat16 smem[];
    __nv_bfloat16* As = smem;
    __nv_bfloat16* Bs = smem + 128 * SPAD;

    const int bm = blockIdx.y;
    const int bn = blockIdx.x;
    const int tid = threadIdx.x;
    const int warp = tid >> 5, lane = tid & 31;
    const int wm = (warp >> 2) * 64;
    const int wn = (warp & 3) * 32;

#pragma unroll
    for (int u = tid; u < 2048; u += 256) {
        int r = u >> 4, c = (u & 15) * 8;
        int grow = bm * 128 + r;
        cp_async16(&As[r * SPAD + c], &g_Hb[(size_t)grow * 128 + c],
                   (grow < Ee) ? 16 : 0);
        cp_async16(&Bs[r * SPAD + c], &g_W2b[(size_t)(bn * 128 + r) * 128 + c], 16);
    }
    cp_commit();
    cp_wait<0>();
    __syncthreads();

    float acc[4][4][4];
#pragma unroll
    for (int mi = 0; mi < 4; mi++)
#pragma unroll
        for (int ni = 0; ni < 4; ni++)
#pragma unroll
            for (int r = 0; r < 4; r++) acc[mi][ni][r] = 0.0f;

    const int lrow = lane & 15;
    const int lcol8 = ((lane >> 4) & 1) * 8;
    const int pbrow = (lane & 7) + ((lane >> 4) & 1) * 8;
    const int pbcol8 = ((lane >> 3) & 1) * 8;

#pragma unroll
    for (int k0 = 0; k0 < 128; k0 += 16) {
        uint32_t a[4][4], b[2][4];
#pragma unroll
        for (int mi = 0; mi < 4; mi++)
            ldsm_x4(a[mi], &As[(wm + mi * 16 + lrow) * SPAD + k0 + lcol8]);
#pragma unroll
        for (int p = 0; p < 2; p++)
            ldsm_x4(b[p], &Bs[(wn + p * 16 + pbrow) * SPAD + k0 + pbcol8]);
#pragma unroll
        for (int mi = 0; mi < 4; mi++)
#pragma unroll
            for (int ni = 0; ni < 4; ni++)
                mma_bf16(acc[mi][ni], a[mi], &b[ni >> 1][(ni & 1) * 2]);
    }
    __syncthreads();

    __nv_bfloat16* stage = As;
    const int r0 = lane >> 2;
    const int c0 = (lane & 3) * 2;
#pragma unroll
    for (int mi = 0; mi < 4; mi++) {
#pragma unroll
        for (int ni = 0; ni < 4; ni++) {
            int cl = wn + ni * 8 + c0;
            float bb0 = b2[bn * 128 + cl], bb1 = b2[bn * 128 + cl + 1];
            int rl = wm + mi * 16 + r0;
            __nv_bfloat162 v;
            v.x = __float2bfloat16_rn(acc[mi][ni][0] + bb0);
            v.y = __float2bfloat16_rn(acc[mi][ni][1] + bb1);
            *(__nv_bfloat162*)&stage[rl * SPAD + cl] = v;
            v.x = __float2bfloat16_rn(acc[mi][ni][2] + bb0);
            v.y = __float2bfloat16_rn(acc[mi][ni][3] + bb1);
            *(__nv_bfloat162*)&stage[(rl + 8) * SPAD + cl] = v;
        }
    }
    __syncthreads();
#pragma unroll
    for (int p = 0; p < 8; p++) {
        int idx = tid + p * 256;
        int row = idx >> 4, c8 = (idx & 15) * 8;
        int grow = bm * 128 + row;
        if (grow < Ee)
            *(uint4*)&g_ewb[(size_t)grow * DDf + bn * 128 + c8] =
                *(const uint4*)&stage[row * SPAD + c8];
    }
}

// ---------------- msgagg v5: 2-warp split-i + 4-edge unrolled streams ------------
__global__ void __launch_bounds__(256) msgagg_kernel(const float* __restrict__ conv_b) {
    __shared__ float comb[4][64];
    const int warp = threadIdx.x >> 5, lane = threadIdx.x & 31;
    const int ln = warp >> 1;
    const int half = warp & 1;
    const int n = blockIdx.x * 4 + ln;
    const bool active = (n < Nn);
    const int j0 = active ? g_eoff[n] : 0;
    const int j1 = active ? g_eoff[n + 1] : 0;
    const int r = lane >> 3;
    const int c8 = (lane & 7) * 8;
    const int ibase = half * 32;
    const unsigned FULL = 0xffffffffu;
    float acc[8];
#pragma unroll
    for (int q = 0; q < 8; q++) acc[q] = 0.0f;

    int j = j0;
    // 4-edge unrolled main loop: 4 independent uint4 streams per t-group
    for (; j + 3 < j1; j += 4) {
        uint32_t xv[4];
        const __nv_bfloat16* wp[4];
#pragma unroll
        for (int u = 0; u < 4; u++) {
            int e = g_perm[j + u];
            int s = g_src[j + u];
            xv[u] = *((const uint32_t*)&g_mh[s * 128 + 64] + lane);
            wp[u] = g_ewb + (size_t)e * DDf + c8;
        }
#pragma unroll
        for (int t = 0; t < 8; t++) {
            int i = ibase + t * 4 + r;
            int sl = half * 16 + 2 * t + (r >> 1);
            uint4 v[4];
#pragma unroll
            for (int u = 0; u < 4; u++)
                v[u] = *(const uint4*)(wp[u] + (size_t)i * 64);
#pragma unroll
            for (int u = 0; u < 4; u++) {
                uint32_t xp = __shfl_sync(FULL, xv[u], sl);
                __nv_bfloat162 xq = *(__nv_bfloat162*)&xp;
                float xi = (r & 1) ? __bfloat162float(xq.y) : __bfloat162float(xq.x);
                const __nv_bfloat162* p = (const __nv_bfloat162*)&v[u];
#pragma unroll
                for (int q = 0; q < 4; q++) {
                    acc[2*q]   = fmaf(xi, __bfloat162float(p[q].x), acc[2*q]);
                    acc[2*q+1] = fmaf(xi, __bfloat162float(p[q].y), acc[2*q+1]);
                }
            }
        }
    }
    // remainder (0..3 edges)
    for (; j < j1; j++) {
        int e0 = g_perm[j], s0 = g_src[j];
        uint32_t xv0 = *((const uint32_t*)&g_mh[s0 * 128 + 64] + lane);
        const __nv_bfloat16* wp0 = g_ewb + (size_t)e0 * DDf + c8;
#pragma unroll
        for (int t = 0; t < 8; t++) {
            int i = ibase + t * 4 + r;
            uint4 v0 = *(const uint4*)(wp0 + (size_t)i * 64);
            int sl = half * 16 + 2 * t + (r >> 1);
            uint32_t xp0 = __shfl_sync(FULL, xv0, sl);
            __nv_bfloat162 xq0 = *(__nv_bfloat162*)&xp0;
            float xi0 = (r & 1) ? __bfloat162float(xq0.y) : __bfloat162float(xq0.x);
            const __nv_bfloat162* p0 = (const __nv_bfloat162*)&v0;
#pragma unroll
            for (int q = 0; q < 4; q++) {
                acc[2*q]   = fmaf(xi0, __bfloat162float(p0[q].x), acc[2*q]);
                acc[2*q+1] = fmaf(xi0, __bfloat162float(p0[q].y), acc[2*q+1]);
            }
        }
    }
#pragma unroll
    for (int q = 0; q < 8; q++) {
        acc[q] += __shfl_xor_sync(FULL, acc[q], 8);
        acc[q] += __shfl_xor_sync(FULL, acc[q], 16);
    }
    if (half == 0 && lane < 8) {
        float4 v0 = make_float4(acc[0], acc[1], acc[2], acc[3]);
        float4 v1 = make_float4(acc[4], acc[5], acc[6], acc[7]);
        *(float4*)&comb[ln][lane * 8]     = v0;
        *(float4*)&comb[ln][lane * 8 + 4] = v1;
    }
    __syncthreads();
    if (half == 1 && lane < 8 && active) {
        float inv = g_invdeg[n];
        const float* cb = &comb[ln][lane * 8];
        __nv_bfloat16 mv[8];
#pragma unroll
        for (int q = 0; q < 8; q++) {
            float m = fmaxf(fmaf(acc[q] + cb[q], inv, conv_b[lane * 8 + q]), 0.0f);
            mv[q] = __float2bfloat16_rn(m);
        }
        *(uint4*)&g_mh[n * 128 + lane * 8] = *(const uint4*)mv;
    }
}

// ---------------- gru_v3 (measured 14us) -----------------------------------------
#define GV_AS 0
#define GV_BS 34816
#define GV_H  (34816 * 4)
#define GV_SMEM (139264 + 34816)   // 174080
__global__ void __launch_bounds__(256, 1) gru_v3(const float* __restrict__ b_ih,
                                                 const float* __restrict__ b_hh) {
    extern __shared__ __align__(16) unsigned char sm[];
    __nv_bfloat16* As = (__nv_bfloat16*)(sm + GV_AS);
    __nv_bfloat16* Bs = (__nv_bfloat16*)(sm + GV_BS);
    float* hs = (float*)(sm + GV_H);

    const int bm = blockIdx.x;
    const int tid = threadIdx.x;
    const int warp = tid >> 5, lane = tid & 31;
    const int wm = (warp >> 2) * 64;
    const int wn = (warp & 3) * 32;

#pragma unroll
    for (int u = tid; u < 2048; u += 256) {
        int r = u >> 4, c = (u & 15) * 8;
        int grow = bm * 128 + r;
        int szA = (grow < Nn) ? 16 : 0;
        cp_async16(&As[r * SPAD + c], &g_mh[(size_t)grow * 128 + c], szA);
        cp_async16(&Bs[(0 * 128 + r) * SPAD + c], &g_WcatT[(0 * 128 + r) * 128 + c], 16);
        cp_async16(&Bs[(1 * 128 + r) * SPAD + c], &g_WcatT[(1 * 128 + r) * 128 + c], 16);
        cp_async16(&Bs[(2 * 128 + r) * SPAD + c], &g_WcatT[(2 * 128 + r) * 128 + c], 16);
        int c4 = (u & 15) * 4;
        cp_async16(&hs[r * 68 + c4], &g_h[(size_t)grow * 64 + c4], szA);
    }
    cp_commit();
    cp_wait<0>();
    __syncthreads();

    const int lrow = lane & 15;
    const int lcol8 = ((lane >> 4) & 1) * 8;
    const int lbrow = lane & 7;
    const int lbcol8 = ((lane >> 3) & 1) * 8;
    const int r0 = lane >> 2;
    const int c0 = (lane & 3) * 2;

    float rgv[4][4][2], zgv[4][4][2];

#pragma unroll
    for (int ch = 0; ch < 3; ch++) {
        const __nv_bfloat16* Bc = Bs + ch * 128 * SPAD;
        float acc[4][4][4];
#pragma unroll
        for (int mi = 0; mi < 4; mi++)
#pragma unroll
            for (int ni = 0; ni < 4; ni++)
#pragma unroll
                for (int r = 0; r < 4; r++) acc[mi][ni][r] = 0.0f;

#pragma unroll
        for (int k0 = 0; k0 < 128; k0 += 16) {
            uint32_t a[4][4], b[4][2];
#pragma unroll
            for (int mi = 0; mi < 4; mi++)
                ldsm_x4(a[mi], &As[(wm + mi * 16 + lrow) * SPAD + k0 + lcol8]);
#pragma unroll
            for (int ni = 0; ni < 4; ni++)
                ldsm_x2(b[ni], &Bc[(wn + ni * 8 + lbrow) * SPAD + k0 + lbcol8]);
#pragma unroll
            for (int mi = 0; mi < 4; mi++)
#pragma unroll
                for (int ni = 0; ni < 4; ni++)
                    mma_bf16(acc[mi][ni], a[mi], b[ni]);
        }

#pragma unroll
        for (int mi = 0; mi < 4; mi++) {
#pragma unroll
            for (int ni = 0; ni < 4; ni++) {
                int d = (wn + ni * 8 + c0) >> 1;
                float bi = b_ih[ch * 64 + d];
                float bh = b_hh[ch * 64 + d];
                if (ch == 0) {
                    rgv[mi][ni][0] = sigmfast(acc[mi][ni][0] + bi + acc[mi][ni][1] + bh);
                    rgv[mi][ni][1] = sigmfast(acc[mi][ni][2] + bi + acc[mi][ni][3] + bh);
                } else if (ch == 1) {
                    zgv[mi][ni][0] = sigmfast(acc[mi][ni][0] + bi + acc[mi][ni][1] + bh);
                    zgv[mi][ni][1] = sigmfast(acc[mi][ni][2] + bi + acc[mi][ni][3] + bh);
                } else {
                    int rl = wm + mi * 16 + r0;
                    int gn0 = bm * 128 + rl;
                    if (gn0 < Nn) {
                        float ng = tanhfast(fmaf(rgv[mi][ni][0], acc[mi][ni][1] + bh,
                                                 acc[mi][ni][0] + bi));
                        float zg = zgv[mi][ni][0];
                        float hv = hs[rl * 68 + d];
                        float h = (1.0f - zg) * ng + zg * hv;
                        g_h[gn0 * 64 + d] = h;
                        g_mh[gn0 * 128 + 64 + d] = __float2bfloat16_rn(h);
                    }
                    int gn1 = gn0 + 8;
                    if (gn1 < Nn) {
                        float ng = tanhfast(fmaf(rgv[mi][ni][1], acc[mi][ni][3] + bh,
                                                 acc[mi][ni][2] + bi));
                        float zg = zgv[mi][ni][1];
                        float hv = hs[(rl + 8) * 68 + d];
                        float h = (1.0f - zg) * ng + zg * hv;
                        g_h[gn1 * 64 + d] = h;
                        g_mh[gn1 * 128 + 64 + d] = __float2bfloat16_rn(h);
                    }
                }
            }
        }
    }
}

// ---------------- fused Set2Set (6 steps) + output MLP — coalesced weights -------
__global__ void __launch_bounds__(256) set2set_kernel(
    const float* __restrict__ b_ih, const float* __restrict__ b_hh,
    const float* __restrict__ lin1_b,
    const float* __restrict__ lin2_w, const float* __restrict__ lin2_b,
    float* __restrict__ out) {
    const int b = blockIdx.x;
    const int tid = threadIdx.x;
    const int lane = tid & 31, w = tid >> 5;
    __shared__ float q[128], hl[64], cl[64], g[256];
    __shared__ float red[8];
    __shared__ float rpart[8][64];
    __shared__ float emax_s, denom_s;
    __shared__ float z[64];

    if (tid < 128) q[tid] = 0.0f;
    if (tid < 64) { hl[tid] = 0.0f; cl[tid] = 0.0f; }
    __syncthreads();

    const int s = g_boff[b], epos = g_boff[b + 1];
    const unsigned FULL = 0xffffffffu;

    for (int step = 0; step < NSTEPS; step++) {
        {
            int j = tid;
            float acc = b_ih[j] + b_hh[j];
#pragma unroll 8
            for (int k = 0; k < 128; k++)
                acc = fmaf(q[k], g_lwihT[k * 256 + j], acc);
#pragma unroll 8
            for (int k = 0; k < 64; k++)
                acc = fmaf(hl[k], g_lwhhT[k * 256 + j], acc);
            g[j] = acc;
        }
        __syncthreads();
        if (tid < 64) {
            int d = tid;
            float ig = g[d], fg = g[64 + d], gg = g[128 + d], og = g[192 + d];
            float c = sigmfast(fg) * cl[d] + sigmfast(ig) * tanhfast(gg);
            cl[d] = c;
            hl[d] = sigmfast(og) * tanhfast(c);
        }
        __syncthreads();

        float lmax = -FLT_MAX;
        for (int n = s + w; n < epos; n += 8) {
            const float* hr = g_h + n * 64;
            float v = hr[lane] * hl[lane] + hr[32 + lane] * hl[32 + lane];
#pragma unroll
            for (int off = 16; off > 0; off >>= 1) v += __shfl_down_sync(FULL, v, off);
            v = __shfl_sync(FULL, v, 0);
            lmax = fmaxf(lmax, v);
        }
        if (lane == 0) red[w] = lmax;
        __syncthreads();
        if (tid == 0) {
            float m = red[0];
#pragma unroll
            for (int i = 1; i < 8; i++) m = fmaxf(m, red[i]);
            emax_s = m;
        }
        __syncthreads();
        float emax = emax_s;

        float lsum = 0.0f, r0 = 0.0f, r1 = 0.0f;
        for (int n = s + w; n < epos; n += 8) {
            const float* hr = g_h + n * 64;
            float x0 = hr[lane], x1 = hr[32 + lane];
            float v = x0 * hl[lane] + x1 * hl[32 + lane];
#pragma unroll
            for (int off = 16; off > 0; off >>= 1) v += __shfl_down_sync(FULL, v, off);
            v = __shfl_sync(FULL, v, 0);
            float ex = __expf(v - emax);
            lsum += ex;
            r0 = fmaf(ex, x0, r0);
            r1 = fmaf(ex, x1, r1);
        }
        if (lane == 0) red[w] = lsum;
        rpart[w][lane] = r0;
        rpart[w][32 + lane] = r1;
        __syncthreads();
        if (tid == 0) {
            float ssum = 0.0f;
#pragma unroll
            for (int i = 0; i < 8; i++) ssum += red[i];
            denom_s = ssum;
        }
        __syncthreads();
        if (tid < 64) {
            float rv = 0.0f;
#pragma unroll
            for (int i = 0; i < 8; i++) rv += rpart[i][tid];
            q[64 + tid] = rv / (denom_s + 1e-16f);
            q[tid] = hl[tid];
        }
        __syncthreads();
    }

    if (tid < 64) {
        float acc = lin1_b[tid];
#pragma unroll 8
        for (int k = 0; k < 128; k++)
            acc = fmaf(q[k], g_l1T[k * 64 + tid], acc);
        z[tid] = fmaxf(acc, 0.0f);
    }
    __syncthreads();
    if (tid < 12) {
        float acc = lin2_b[tid];
        const float* wr = lin2_w + tid * 64;
#pragma unroll
        for (int d = 0; d < 64; d++) acc = fmaf(z[d], wr[d], acc);
        out[b * 12 + tid] = acc;
    }
}

// ---------------- launch ----------------
extern "C" void kernel_launch(void* const* d_in, const int* in_sizes, int n_in,
                              void* d_out, int out_size) {
    const float* x         = (const float*)d_in[0];
    const float* edge_attr = (const float*)d_in[1];
    const int*   edge_index= (const int*)  d_in[2];
    const int*   batch     = (const int*)  d_in[3];
    const float* lin0_w    = (const float*)d_in[4];
    const float* lin0_b    = (const float*)d_in[5];
    const float* en_w1     = (const float*)d_in[6];
    const float* en_b1     = (const float*)d_in[7];
    const float* en_w2     = (const float*)d_in[8];
    const float* en_b2     = (const float*)d_in[9];
    const float* conv_b    = (const float*)d_in[10];
    const float* gru_w_ih  = (const float*)d_in[11];
    const float* gru_w_hh  = (const float*)d_in[12];
    const float* gru_b_ih  = (const float*)d_in[13];
    const float* gru_b_hh  = (const float*)d_in[14];
    const float* lstm_w_ih = (const float*)d_in[15];
    const float* lstm_w_hh = (const float*)d_in[16];
    const float* lstm_b_ih = (const float*)d_in[17];
    const float* lstm_b_hh = (const float*)d_in[18];
    const float* lin1_w    = (const float*)d_in[19];
    const float* lin1_b    = (const float*)d_in[20];
    const float* lin2_w    = (const float*)d_in[21];
    const float* lin2_b    = (const float*)d_in[22];
    float* out = (float*)d_out;

    const int gemm_smem = 2 * 128 * SPAD * (int)sizeof(__nv_bfloat16);  // 69632
    const int prep_smem = 2 * Nn * (int)sizeof(int);                    // 120000
    cudaFuncSetAttribute(gemm_ew_mma, cudaFuncAttributeMaxDynamicSharedMemorySize,
                         gemm_smem);
    cudaFuncSetAttribute(gru_v3, cudaFuncAttributeMaxDynamicSharedMemorySize,
                         GV_SMEM);
    cudaFuncSetAttribute(prep_csr_kernel, cudaFuncAttributeMaxDynamicSharedMemorySize,
                         prep_smem);

    prep_csr_kernel<<<PREP_BLOCKS, 1024, prep_smem>>>(
        x, lin0_w, lin0_b, en_w2, edge_attr, en_w1, en_b1,
        gru_w_ih, gru_w_hh, batch, edge_index,
        lstm_w_ih, lstm_w_hh, lin1_w);
    dim3 gemm_grid(DDf / 128, (Ee + 127) / 128);
    gemm_ew_mma<<<gemm_grid, 256, gemm_smem>>>(en_b2);

    for (int s = 0; s < NSTEPS; s++) {
        msgagg_kernel<<<(Nn + 3) / 4, 256>>>(conv_b);
        gru_v3<<<(Nn + 127) / 128, 256, GV_SMEM>>>(gru_b_ih, gru_b_hh);
    }

    set2set_kernel<<<Bb, 256>>>(lstm_b_ih, lstm_b_hh,
                                lin1_b, lin2_w, lin2_b, out);
}